// round 15
// baseline (speedup 1.0000x reference)
#include <cuda_runtime.h>
#include <cuda_bf16.h>
#include <cstdint>

#define NB 128
#define C 64
#define T 1024
#define TILE 128
#define NSUB 16          // 64-row s-subtiles

// bf16 scratch, ALL t-major [n][t][c]; Q has scale*log2e folded in.
__device__ __nv_bfloat16 g_Qb[NB * T * C];
__device__ __nv_bfloat16 g_Kb[NB * T * C];
__device__ __nv_bfloat16 g_Vb[NB * T * C];

__device__ __forceinline__ float ex2a(float x) {
    float y;
    asm("ex2.approx.ftz.f32 %0, %1;" : "=f"(y) : "f"(x));
    return y;
}
__device__ __forceinline__ uint32_t packbf(float lo, float hi) {
    __nv_bfloat162 v = __floats2bfloat162_rn(lo, hi);
    return *(uint32_t*)&v;
}
__device__ __forceinline__ uint32_t smaddr(const void* p) {
    uint32_t a;
    asm("{ .reg .u64 t; cvta.to.shared.u64 t, %1; cvt.u32.u64 %0, t; }" : "=r"(a) : "l"(p));
    return a;
}
__device__ __forceinline__ void cpa16(uint32_t dst, const void* src) {
    asm volatile("cp.async.cg.shared.global [%0], [%1], 16;" :: "r"(dst), "l"(src));
}
#define CP_COMMIT() asm volatile("cp.async.commit_group;" ::: "memory")
#define CP_WAIT(n)  asm volatile("cp.async.wait_group %0;" :: "n"(n) : "memory")

#define MMA_BF16(d, a0, a1, a2, a3, b0, b1)                                   \
    asm volatile(                                                             \
        "mma.sync.aligned.m16n8k16.row.col.f32.bf16.bf16.f32 "                \
        "{%0,%1,%2,%3}, {%4,%5,%6,%7}, {%8,%9}, {%0,%1,%2,%3};"               \
        : "+f"(d[0]), "+f"(d[1]), "+f"(d[2]), "+f"(d[3])                      \
        : "r"(a0), "r"(a1), "r"(a2), "r"(a3), "r"(b0), "r"(b1))

#define LDSM4(R, a)                                                           \
    asm volatile("ldmatrix.sync.aligned.m8n8.x4.shared.b16 {%0,%1,%2,%3}, [%4];" \
        : "=r"((R)[0]), "=r"((R)[1]), "=r"((R)[2]), "=r"((R)[3]) : "r"(a))

#define LDSM4T(R, a)                                                          \
    asm volatile("ldmatrix.sync.aligned.m8n8.x4.trans.shared.b16 {%0,%1,%2,%3}, [%4];" \
        : "=r"((R)[0]), "=r"((R)[1]), "=r"((R)[2]), "=r"((R)[3]) : "r"(a))

// ---------------------------------------------------------------------------
// Kernel 1: QKV projection (unchanged from R14). 128 threads, 3 CTAs/SM.
// smem: xs [64][136] + Ws 3x[64][72] + stg [128][72] = 63488 B.
// ---------------------------------------------------------------------------
#define XS_O  0
#define WS_O  8704
#define STG_O 22528
#define QKV_SMEM_BF (STG_O + 9216)     // 31744 bf16 = 63488 B

extern "C" __global__ void __launch_bounds__(128, 3)
qkv_kernel(const float* __restrict__ x,
           const float* __restrict__ Wq,
           const float* __restrict__ Wk,
           const float* __restrict__ Wv,
           const float* __restrict__ scale_p)
{
    extern __shared__ __nv_bfloat16 smb[];
    __nv_bfloat16* xs  = smb + XS_O;
    __nv_bfloat16* Ws  = smb + WS_O;
    __nv_bfloat16* stg = smb + STG_O;

    const int j = blockIdx.x, n = blockIdx.y;
    const int tid = threadIdx.x;
    const int warp = tid >> 5, lane = tid & 31;
    const int g = lane >> 2, c4 = lane & 3;
    const int rb = warp * 32;
    const float qs = scale_p[0] * 1.44269504088896f;

    const int brow = (lane >> 4) * 8 + (lane & 7);
    const int bcol = ((lane >> 3) & 1) * 8;
    const int tkrow = ((lane >> 4) & 1) * 8 + (lane & 7);
    const int tmcol = ((lane >> 3) & 1) * 8;

    const float* xb = x + (size_t)n * C * T + j * TILE;
    for (int idx = tid; idx < 2048; idx += 128) {
        int c = idx >> 5, t4 = (idx & 31) * 4;
        float4 v = *(const float4*)&xb[c * T + t4];
        *(uint32_t*)&xs[c * 136 + t4]     = packbf(v.x, v.y);
        *(uint32_t*)&xs[c * 136 + t4 + 2] = packbf(v.z, v.w);
    }
    for (int idx = tid; idx < 1024; idx += 128) {
        int o = idx >> 4, cc = (idx & 15) * 4;
        float4 wq = *(const float4*)&Wq[o * 64 + cc];
        float4 wk = *(const float4*)&Wk[o * 64 + cc];
        float4 wv = *(const float4*)&Wv[o * 64 + cc];
        *(uint32_t*)&Ws[o * 72 + cc]            = packbf(wq.x, wq.y);
        *(uint32_t*)&Ws[o * 72 + cc + 2]        = packbf(wq.z, wq.w);
        *(uint32_t*)&Ws[4608 + o * 72 + cc]     = packbf(wk.x, wk.y);
        *(uint32_t*)&Ws[4608 + o * 72 + cc + 2] = packbf(wk.z, wk.w);
        *(uint32_t*)&Ws[9216 + o * 72 + cc]     = packbf(wv.x, wv.y);
        *(uint32_t*)&Ws[9216 + o * 72 + cc + 2] = packbf(wv.z, wv.w);
    }
    __syncthreads();

    const uint32_t sX = smaddr(xs);
    const uint32_t sW = smaddr(Ws);
    const uint32_t aX0 = sX + (tkrow * 136 + rb + tmcol) * 2;
    const uint32_t aX1 = aX0 + 16 * 2;

    for (int m = 0; m < 3; m++) {
        float acc[2][8][4];
#pragma unroll
        for (int mb = 0; mb < 2; mb++)
#pragma unroll
            for (int i = 0; i < 8; i++)
#pragma unroll
                for (int k = 0; k < 4; k++) acc[mb][i][k] = 0.f;

        const uint32_t wbase = sW + m * 4608 * 2;
#pragma unroll
        for (int ks4 = 0; ks4 < 4; ks4++) {
            uint32_t A0[4], A1[4];
            LDSM4T(A0, aX0 + ks4 * (16 * 136 * 2));
            LDSM4T(A1, aX1 + ks4 * (16 * 136 * 2));
#pragma unroll
            for (int nf2 = 0; nf2 < 4; nf2++) {
                uint32_t Bv[4];
                LDSM4(Bv, wbase + ((nf2 * 16 + brow) * 72 + bcol + ks4 * 16) * 2);
                MMA_BF16(acc[0][nf2 * 2],     A0[0], A0[1], A0[2], A0[3], Bv[0], Bv[1]);
                MMA_BF16(acc[1][nf2 * 2],     A1[0], A1[1], A1[2], A1[3], Bv[0], Bv[1]);
                MMA_BF16(acc[0][nf2 * 2 + 1], A0[0], A0[1], A0[2], A0[3], Bv[2], Bv[3]);
                MMA_BF16(acc[1][nf2 * 2 + 1], A1[0], A1[1], A1[2], A1[3], Bv[2], Bv[3]);
            }
        }

        if (m == 0) {
#pragma unroll
            for (int mb = 0; mb < 2; mb++)
#pragma unroll
                for (int i = 0; i < 8; i++)
#pragma unroll
                    for (int k = 0; k < 4; k++) acc[mb][i][k] *= qs;
        }

        if (m > 0) __syncthreads();
#pragma unroll
        for (int mb = 0; mb < 2; mb++) {
            int r0 = rb + mb * 16 + g, r1 = r0 + 8;
#pragma unroll
            for (int nf = 0; nf < 8; nf++) {
                int o = nf * 8 + 2 * c4;
                *(uint32_t*)&stg[r0 * 72 + o] = packbf(acc[mb][nf][0], acc[mb][nf][1]);
                *(uint32_t*)&stg[r1 * 72 + o] = packbf(acc[mb][nf][2], acc[mb][nf][3]);
            }
        }
        __syncthreads();
        __nv_bfloat16* dst = (m == 0 ? g_Qb : (m == 1 ? g_Kb : g_Vb))
                             + ((size_t)n * T + j * TILE) * C;
#pragma unroll
        for (int it = 0; it < 8; it++) {
            int flat = it * 1024 + tid * 8;
            int r = flat >> 6, c = flat & 63;
            *(float4*)&dst[r * 64 + c] = *(const float4*)&stg[r * 72 + c];
        }
    }
}

// ---------------------------------------------------------------------------
// Kernel 2: attention. 128 threads (4 warps x m32). P in registers (FA2),
// 64-row s-subtiles, 3-stage cp.async pipeline, ONE barrier per subtile.
// smem: Qs[128][72] + 3 stages x (K[64][72] + V[64][72]) = 73728 B. 3 CTAs/SM.
// ---------------------------------------------------------------------------
#define AQS_O 0
#define AB_O  9216                      // bf16 offset of stage buffers
#define STAGE_B 18432                   // bytes per stage (K64 + V64)
#define NSTG 3
#define ATTN_SMEM_BF (AB_O + NSTG * 9216)  // 36864 bf16 = 73728 B

__device__ __forceinline__ void stage_load(uint32_t dstbase,
                                           const __nv_bfloat16* ks,
                                           const __nv_bfloat16* vs, int tid) {
#pragma unroll
    for (int it = 0; it < 4; it++) {
        int flat = it * 128 + tid;
        int r = flat >> 3, cg = flat & 7;
        uint32_t off = (uint32_t)(r * 72 + cg * 8) * 2;
        cpa16(dstbase + off,        ks + r * 64 + cg * 8);
        cpa16(dstbase + 9216 + off, vs + r * 64 + cg * 8);
    }
}

extern "C" __global__ void __launch_bounds__(128, 3)
attn_kernel(const float* __restrict__ x,
            const float* __restrict__ Wo,
            float* __restrict__ out)
{
    extern __shared__ __nv_bfloat16 smb[];
    __nv_bfloat16* Qs = smb + AQS_O;

    const int j = blockIdx.x, n = blockIdx.y;
    const int tid = threadIdx.x;
    const int warp = tid >> 5, lane = tid & 31;
    const int g = lane >> 2, c4 = lane & 3;
    const int rb = warp * 32;

    // ldmatrix lane roles
    const int arow = ((lane >> 3) & 1) * 8 + (lane & 7);  // A rows / trans-B rows
    const int acol = (lane >> 4) * 8;                     // A col offset
    const int brow = (lane >> 4) * 8 + (lane & 7);        // B rows (non-trans)
    const int bcol = ((lane >> 3) & 1) * 8;               // B col offset
    const int vcol = (lane >> 4) * 8;                     // trans-B col offset

    const uint32_t sQ = smaddr(Qs);
    const uint32_t sB = smaddr(smb + AB_O);

    const __nv_bfloat16* kbase = g_Kb + (size_t)n * T * C;
    const __nv_bfloat16* vbase = g_Vb + (size_t)n * T * C;

    // prefetch stages 0 and 1
    stage_load(sB, kbase, vbase, tid);
    CP_COMMIT();
    stage_load(sB + STAGE_B, kbase + 64 * C, vbase + 64 * C, tid);
    CP_COMMIT();

    // load Q tile [128][64] bf16 -> stride 72 (overlaps with prefetches)
    const __nv_bfloat16* qsrc = g_Qb + ((size_t)n * T + j * TILE) * C;
#pragma unroll
    for (int it = 0; it < 8; it++) {
        int flat = it * 1024 + tid * 8;
        int r = flat >> 6, c = flat & 63;
        float4 v = *(const float4*)&qsrc[flat];
        *(float4*)&Qs[r * 72 + c] = v;
    }

    float lsum[2][2] = {{0.f, 0.f}, {0.f, 0.f}};
    float oacc[2][8][4];
#pragma unroll
    for (int mb = 0; mb < 2; mb++)
#pragma unroll
        for (int i = 0; i < 8; i++)
#pragma unroll
            for (int k = 0; k < 4; k++) oacc[mb][i][k] = 0.f;

    const uint32_t aQ0 = sQ + ((rb + arow) * 72 + acol) * 2;
    const uint32_t aQ1 = aQ0 + 16 * 72 * 2;

    for (int ss = 0; ss < NSUB; ss++) {
        // stage ss arrived (group for ss+1 may still be in flight)
        if (ss < NSUB - 1) { CP_WAIT(1); } else { CP_WAIT(0); }
        // ONE barrier: (a) stage ss visible to all warps; (b) certifies all
        // warps finished compute(ss-1), so buffer (ss+2)%3 == (ss-1)%3 is free.
        __syncthreads();
        if (ss + 2 < NSUB) {
            stage_load(sB + ((ss + 2) % NSTG) * STAGE_B,
                       kbase + (size_t)(ss + 2) * 64 * C,
                       vbase + (size_t)(ss + 2) * 64 * C, tid);
            CP_COMMIT();
        }

        const uint32_t sK = sB + (ss % NSTG) * STAGE_B;
        const uint32_t sV = sK + 9216;

        // S = Q K^T (m32 x n64 x k64)
        float sacc[2][8][4];
#pragma unroll
        for (int mb = 0; mb < 2; mb++)
#pragma unroll
            for (int i = 0; i < 8; i++)
#pragma unroll
                for (int k = 0; k < 4; k++) sacc[mb][i][k] = 0.f;

#pragma unroll
        for (int ks4 = 0; ks4 < 4; ks4++) {
            uint32_t A0[4], A1[4];
            LDSM4(A0, aQ0 + ks4 * 32);
            LDSM4(A1, aQ1 + ks4 * 32);
#pragma unroll
            for (int nf2 = 0; nf2 < 4; nf2++) {
                uint32_t Bv[4];
                LDSM4(Bv, sK + ((nf2 * 16 + brow) * 72 + bcol + ks4 * 16) * 2);
                MMA_BF16(sacc[0][nf2 * 2],     A0[0], A0[1], A0[2], A0[3], Bv[0], Bv[1]);
                MMA_BF16(sacc[1][nf2 * 2],     A1[0], A1[1], A1[2], A1[3], Bv[0], Bv[1]);
                MMA_BF16(sacc[0][nf2 * 2 + 1], A0[0], A0[1], A0[2], A0[3], Bv[2], Bv[3]);
                MMA_BF16(sacc[1][nf2 * 2 + 1], A1[0], A1[1], A1[2], A1[3], Bv[2], Bv[3]);
            }
        }

        // exp2 + row-sum + pack: S acc fragment -> PV A fragment
        uint32_t pfrag[2][4][4];
#pragma unroll
        for (int mb = 0; mb < 2; mb++) {
#pragma unroll
            for (int jj = 0; jj < 4; jj++) {
                float e00 = ex2a(sacc[mb][2 * jj][0]);
                float e01 = ex2a(sacc[mb][2 * jj][1]);
                float e02 = ex2a(sacc[mb][2 * jj][2]);
                float e03 = ex2a(sacc[mb][2 * jj][3]);
                float e10 = ex2a(sacc[mb][2 * jj + 1][0]);
                float e11 = ex2a(sacc[mb][2 * jj + 1][1]);
                float e12 = ex2a(sacc[mb][2 * jj + 1][2]);
                float e13 = ex2a(sacc[mb][2 * jj + 1][3]);
                lsum[mb][0] += (e00 + e01) + (e10 + e11);
                lsum[mb][1] += (e02 + e03) + (e12 + e13);
                pfrag[mb][jj][0] = packbf(e00, e01);
                pfrag[mb][jj][1] = packbf(e02, e03);
                pfrag[mb][jj][2] = packbf(e10, e11);
                pfrag[mb][jj][3] = packbf(e12, e13);
            }
        }

        // O += P V (m32 x n64 x k64), V t-major via trans ldmatrix
#pragma unroll
        for (int jj = 0; jj < 4; jj++) {
#pragma unroll
            for (int nf2 = 0; nf2 < 4; nf2++) {
                uint32_t Bv[4];
                LDSM4T(Bv, sV + ((jj * 16 + arow) * 72 + nf2 * 16 + vcol) * 2);
                MMA_BF16(oacc[0][nf2 * 2],     pfrag[0][jj][0], pfrag[0][jj][1],
                         pfrag[0][jj][2], pfrag[0][jj][3], Bv[0], Bv[1]);
                MMA_BF16(oacc[1][nf2 * 2],     pfrag[1][jj][0], pfrag[1][jj][1],
                         pfrag[1][jj][2], pfrag[1][jj][3], Bv[0], Bv[1]);
                MMA_BF16(oacc[0][nf2 * 2 + 1], pfrag[0][jj][0], pfrag[0][jj][1],
                         pfrag[0][jj][2], pfrag[0][jj][3], Bv[2], Bv[3]);
                MMA_BF16(oacc[1][nf2 * 2 + 1], pfrag[1][jj][0], pfrag[1][jj][1],
                         pfrag[1][jj][2], pfrag[1][jj][3], Bv[2], Bv[3]);
            }
        }
    }

    // row sums -> normalize
#pragma unroll
    for (int mb = 0; mb < 2; mb++)
#pragma unroll
        for (int h = 0; h < 2; h++) {
            lsum[mb][h] += __shfl_xor_sync(0xffffffffu, lsum[mb][h], 1);
            lsum[mb][h] += __shfl_xor_sync(0xffffffffu, lsum[mb][h], 2);
        }
    float inv00 = 1.0f / lsum[0][0], inv01 = 1.0f / lsum[0][1];
    float inv10 = 1.0f / lsum[1][0], inv11 = 1.0f / lsum[1][1];

    // O (bf16, normalized) -> Qs (own rows) as [tq][c]
#pragma unroll
    for (int mb = 0; mb < 2; mb++) {
        int r0 = rb + mb * 16 + g, r1 = r0 + 8;
        float i0 = mb ? inv10 : inv00, i1 = mb ? inv11 : inv01;
#pragma unroll
        for (int nf = 0; nf < 8; nf++) {
            int o = nf * 8 + 2 * c4;
            *(uint32_t*)&Qs[r0 * 72 + o] = packbf(oacc[mb][nf][0] * i0, oacc[mb][nf][1] * i0);
            *(uint32_t*)&Qs[r1 * 72 + o] = packbf(oacc[mb][nf][2] * i1, oacc[mb][nf][3] * i1);
        }
    }
    // Wo -> stage region (dead) as [o][c] bf16 stride 72
    __nv_bfloat16* Wos = smb + AB_O;
#pragma unroll
    for (int it = 0; it < 8; it++) {
        int flat = it * 512 + tid * 4;
        int o = flat >> 6, c = flat & 63;
        float4 w = *(const float4*)&Wo[flat];
        *(uint32_t*)&Wos[o * 72 + c]     = packbf(w.x, w.y);
        *(uint32_t*)&Wos[o * 72 + c + 2] = packbf(w.z, w.w);
    }
    __syncthreads();

    // D2 = O * Wo^T : m32 n64 k64
    const uint32_t sWo = smaddr(Wos);
    const uint32_t aO0 = sQ + ((rb + arow) * 72 + acol) * 2;
    const uint32_t aO1 = aO0 + 16 * 72 * 2;
    float pacc[2][8][4];
#pragma unroll
    for (int mb = 0; mb < 2; mb++)
#pragma unroll
        for (int i = 0; i < 8; i++)
#pragma unroll
            for (int k = 0; k < 4; k++) pacc[mb][i][k] = 0.f;

#pragma unroll
    for (int ks4 = 0; ks4 < 4; ks4++) {
        uint32_t A0[4], A1[4];
        LDSM4(A0, aO0 + ks4 * 32);
        LDSM4(A1, aO1 + ks4 * 32);
#pragma unroll
        for (int nf2 = 0; nf2 < 4; nf2++) {
            uint32_t Bv[4];
            LDSM4(Bv, sWo + ((nf2 * 16 + brow) * 72 + bcol + ks4 * 16) * 2);
            MMA_BF16(pacc[0][nf2 * 2],     A0[0], A0[1], A0[2], A0[3], Bv[0], Bv[1]);
            MMA_BF16(pacc[1][nf2 * 2],     A1[0], A1[1], A1[2], A1[3], Bv[0], Bv[1]);
            MMA_BF16(pacc[0][nf2 * 2 + 1], A0[0], A0[1], A0[2], A0[3], Bv[2], Bv[3]);
            MMA_BF16(pacc[1][nf2 * 2 + 1], A1[0], A1[1], A1[2], A1[3], Bv[2], Bv[3]);
        }
    }
    __syncthreads();   // all warps done reading Wos before Pf overwrites

    // stage transposed as fp32 [o][t] stride 132 over the stage region:
    // bytes 18432..52224 of 73728-B smem (Qs untouched).
    float* Pf = (float*)(smb + AB_O);
#pragma unroll
    for (int mb = 0; mb < 2; mb++) {
        int t0 = rb + mb * 16 + g, t1 = t0 + 8;
#pragma unroll
        for (int nf = 0; nf < 8; nf++) {
            int o = nf * 8 + 2 * c4;
            Pf[o * 132 + t0]       = pacc[mb][nf][0];
            Pf[(o + 1) * 132 + t0] = pacc[mb][nf][1];
            Pf[o * 132 + t1]       = pacc[mb][nf][2];
            Pf[(o + 1) * 132 + t1] = pacc[mb][nf][3];
        }
    }
    __syncthreads();

    // out[o][t] = proj + x, coalesced float4
    const float* xb = x + (size_t)n * C * T + j * TILE;
    float* ob = out + (size_t)n * C * T + j * TILE;
#pragma unroll
    for (int it = 0; it < 16; it++) {
        int flat = it * 512 + tid * 4;
        int o = flat >> 7, t = flat & 127;
        float4 v  = *(const float4*)&Pf[o * 132 + t];
        float4 xr = *(const float4*)&xb[o * T + t];
        float4 r  = make_float4(v.x + xr.x, v.y + xr.y, v.z + xr.z, v.w + xr.w);
        *(float4*)&ob[o * T + t] = r;
    }
}

// ---------------------------------------------------------------------------
extern "C" void kernel_launch(void* const* d_in, const int* in_sizes, int n_in,
                              void* d_out, int out_size)
{
    const float* x     = (const float*)d_in[0];
    const float* Wq    = (const float*)d_in[1];
    const float* Wk    = (const float*)d_in[2];
    const float* Wv    = (const float*)d_in[3];
    const float* Wo    = (const float*)d_in[4];
    const float* scale = (const float*)d_in[5];
    float* out = (float*)d_out;

    const int smem1 = QKV_SMEM_BF * 2;     // 63488 B
    const int smem2 = ATTN_SMEM_BF * 2;    // 73728 B
    cudaFuncSetAttribute(qkv_kernel,  cudaFuncAttributeMaxDynamicSharedMemorySize, smem1);
    cudaFuncSetAttribute(attn_kernel, cudaFuncAttributeMaxDynamicSharedMemorySize, smem2);

    dim3 grid(8, 128);
    qkv_kernel<<<grid, 128, smem1>>>(x, Wq, Wk, Wv, scale);
    attn_kernel<<<grid, 128, smem2>>>(x, Wo, out);
}

// round 16
// speedup vs baseline: 1.0034x; 1.0034x over previous
#include <cuda_runtime.h>
#include <cuda_bf16.h>
#include <cuda_fp16.h>
#include <cstdint>

#define NB 128
#define C 64
#define T 1024
#define TILE 128
#define NSUB 16          // 64-row s-subtiles

// Scratch, ALL t-major [n][t][c]; Q has scale*log2e folded in.
// Q,K hold bf16; V holds fp16 bits (byte-copied everywhere).
__device__ __nv_bfloat16 g_Qb[NB * T * C];
__device__ __nv_bfloat16 g_Kb[NB * T * C];
__device__ __nv_bfloat16 g_Vb[NB * T * C];   // fp16 payload

__device__ __forceinline__ uint32_t packbf(float lo, float hi) {
    __nv_bfloat162 v = __floats2bfloat162_rn(lo, hi);
    return *(uint32_t*)&v;
}
__device__ __forceinline__ uint32_t packhf(float lo, float hi) {
    uint32_t r;
    asm("cvt.rn.f16x2.f32 %0, %2, %1;" : "=r"(r) : "f"(lo), "f"(hi));
    return r;
}
__device__ __forceinline__ uint32_t ex2h2(uint32_t x) {
    uint32_t y;
    asm("ex2.approx.f16x2 %0, %1;" : "=r"(y) : "r"(x));
    return y;
}
__device__ __forceinline__ uint32_t smaddr(const void* p) {
    uint32_t a;
    asm("{ .reg .u64 t; cvta.to.shared.u64 t, %1; cvt.u32.u64 %0, t; }" : "=r"(a) : "l"(p));
    return a;
}
__device__ __forceinline__ void cpa16(uint32_t dst, const void* src) {
    asm volatile("cp.async.cg.shared.global [%0], [%1], 16;" :: "r"(dst), "l"(src));
}
#define CP_COMMIT() asm volatile("cp.async.commit_group;" ::: "memory")
#define CP_WAIT(n)  asm volatile("cp.async.wait_group %0;" :: "n"(n) : "memory")

#define MMA_BF16(d, a0, a1, a2, a3, b0, b1)                                   \
    asm volatile(                                                             \
        "mma.sync.aligned.m16n8k16.row.col.f32.bf16.bf16.f32 "                \
        "{%0,%1,%2,%3}, {%4,%5,%6,%7}, {%8,%9}, {%0,%1,%2,%3};"               \
        : "+f"(d[0]), "+f"(d[1]), "+f"(d[2]), "+f"(d[3])                      \
        : "r"(a0), "r"(a1), "r"(a2), "r"(a3), "r"(b0), "r"(b1))

#define MMA_F16(d, a0, a1, a2, a3, b0, b1)                                    \
    asm volatile(                                                             \
        "mma.sync.aligned.m16n8k16.row.col.f32.f16.f16.f32 "                  \
        "{%0,%1,%2,%3}, {%4,%5,%6,%7}, {%8,%9}, {%0,%1,%2,%3};"               \
        : "+f"(d[0]), "+f"(d[1]), "+f"(d[2]), "+f"(d[3])                      \
        : "r"(a0), "r"(a1), "r"(a2), "r"(a3), "r"(b0), "r"(b1))

#define LDSM4(R, a)                                                           \
    asm volatile("ldmatrix.sync.aligned.m8n8.x4.shared.b16 {%0,%1,%2,%3}, [%4];" \
        : "=r"((R)[0]), "=r"((R)[1]), "=r"((R)[2]), "=r"((R)[3]) : "r"(a))

#define LDSM4T(R, a)                                                          \
    asm volatile("ldmatrix.sync.aligned.m8n8.x4.trans.shared.b16 {%0,%1,%2,%3}, [%4];" \
        : "=r"((R)[0]), "=r"((R)[1]), "=r"((R)[2]), "=r"((R)[3]) : "r"(a))

// ---------------------------------------------------------------------------
// Kernel 1: QKV projection (R14 structure; V staged as fp16). 128 thr, 3 CTA/SM.
// smem: xs [64][136] + Ws 3x[64][72] + stg [128][72] = 63488 B.
// ---------------------------------------------------------------------------
#define XS_O  0
#define WS_O  8704
#define STG_O 22528
#define QKV_SMEM_BF (STG_O + 9216)     // 31744 bf16 = 63488 B

extern "C" __global__ void __launch_bounds__(128, 3)
qkv_kernel(const float* __restrict__ x,
           const float* __restrict__ Wq,
           const float* __restrict__ Wk,
           const float* __restrict__ Wv,
           const float* __restrict__ scale_p)
{
    extern __shared__ __nv_bfloat16 smb[];
    __nv_bfloat16* xs  = smb + XS_O;
    __nv_bfloat16* Ws  = smb + WS_O;
    __nv_bfloat16* stg = smb + STG_O;

    const int j = blockIdx.x, n = blockIdx.y;
    const int tid = threadIdx.x;
    const int warp = tid >> 5, lane = tid & 31;
    const int g = lane >> 2, c4 = lane & 3;
    const int rb = warp * 32;
    const float qs = scale_p[0] * 1.44269504088896f;

    const int brow = (lane >> 4) * 8 + (lane & 7);
    const int bcol = ((lane >> 3) & 1) * 8;
    const int tkrow = ((lane >> 4) & 1) * 8 + (lane & 7);
    const int tmcol = ((lane >> 3) & 1) * 8;

    const float* xb = x + (size_t)n * C * T + j * TILE;
    for (int idx = tid; idx < 2048; idx += 128) {
        int c = idx >> 5, t4 = (idx & 31) * 4;
        float4 v = *(const float4*)&xb[c * T + t4];
        *(uint32_t*)&xs[c * 136 + t4]     = packbf(v.x, v.y);
        *(uint32_t*)&xs[c * 136 + t4 + 2] = packbf(v.z, v.w);
    }
    for (int idx = tid; idx < 1024; idx += 128) {
        int o = idx >> 4, cc = (idx & 15) * 4;
        float4 wq = *(const float4*)&Wq[o * 64 + cc];
        float4 wk = *(const float4*)&Wk[o * 64 + cc];
        float4 wv = *(const float4*)&Wv[o * 64 + cc];
        *(uint32_t*)&Ws[o * 72 + cc]            = packbf(wq.x, wq.y);
        *(uint32_t*)&Ws[o * 72 + cc + 2]        = packbf(wq.z, wq.w);
        *(uint32_t*)&Ws[4608 + o * 72 + cc]     = packbf(wk.x, wk.y);
        *(uint32_t*)&Ws[4608 + o * 72 + cc + 2] = packbf(wk.z, wk.w);
        *(uint32_t*)&Ws[9216 + o * 72 + cc]     = packbf(wv.x, wv.y);
        *(uint32_t*)&Ws[9216 + o * 72 + cc + 2] = packbf(wv.z, wv.w);
    }
    __syncthreads();

    const uint32_t sX = smaddr(xs);
    const uint32_t sW = smaddr(Ws);
    const uint32_t aX0 = sX + (tkrow * 136 + rb + tmcol) * 2;
    const uint32_t aX1 = aX0 + 16 * 2;

    for (int m = 0; m < 3; m++) {
        float acc[2][8][4];
#pragma unroll
        for (int mb = 0; mb < 2; mb++)
#pragma unroll
            for (int i = 0; i < 8; i++)
#pragma unroll
                for (int k = 0; k < 4; k++) acc[mb][i][k] = 0.f;

        const uint32_t wbase = sW + m * 4608 * 2;
#pragma unroll
        for (int ks4 = 0; ks4 < 4; ks4++) {
            uint32_t A0[4], A1[4];
            LDSM4T(A0, aX0 + ks4 * (16 * 136 * 2));
            LDSM4T(A1, aX1 + ks4 * (16 * 136 * 2));
#pragma unroll
            for (int nf2 = 0; nf2 < 4; nf2++) {
                uint32_t Bv[4];
                LDSM4(Bv, wbase + ((nf2 * 16 + brow) * 72 + bcol + ks4 * 16) * 2);
                MMA_BF16(acc[0][nf2 * 2],     A0[0], A0[1], A0[2], A0[3], Bv[0], Bv[1]);
                MMA_BF16(acc[1][nf2 * 2],     A1[0], A1[1], A1[2], A1[3], Bv[0], Bv[1]);
                MMA_BF16(acc[0][nf2 * 2 + 1], A0[0], A0[1], A0[2], A0[3], Bv[2], Bv[3]);
                MMA_BF16(acc[1][nf2 * 2 + 1], A1[0], A1[1], A1[2], A1[3], Bv[2], Bv[3]);
            }
        }

        if (m == 0) {
#pragma unroll
            for (int mb = 0; mb < 2; mb++)
#pragma unroll
                for (int i = 0; i < 8; i++)
#pragma unroll
                    for (int k = 0; k < 4; k++) acc[mb][i][k] *= qs;
        }

        if (m > 0) __syncthreads();
#pragma unroll
        for (int mb = 0; mb < 2; mb++) {
            int r0 = rb + mb * 16 + g, r1 = r0 + 8;
#pragma unroll
            for (int nf = 0; nf < 8; nf++) {
                int o = nf * 8 + 2 * c4;
                if (m == 2) {   // V: fp16 payload
                    *(uint32_t*)&stg[r0 * 72 + o] = packhf(acc[mb][nf][0], acc[mb][nf][1]);
                    *(uint32_t*)&stg[r1 * 72 + o] = packhf(acc[mb][nf][2], acc[mb][nf][3]);
                } else {        // Q/K: bf16
                    *(uint32_t*)&stg[r0 * 72 + o] = packbf(acc[mb][nf][0], acc[mb][nf][1]);
                    *(uint32_t*)&stg[r1 * 72 + o] = packbf(acc[mb][nf][2], acc[mb][nf][3]);
                }
            }
        }
        __syncthreads();
        __nv_bfloat16* dst = (m == 0 ? g_Qb : (m == 1 ? g_Kb : g_Vb))
                             + ((size_t)n * T + j * TILE) * C;
#pragma unroll
        for (int it = 0; it < 8; it++) {
            int flat = it * 1024 + tid * 8;
            int r = flat >> 6, c = flat & 63;
            *(float4*)&dst[r * 64 + c] = *(const float4*)&stg[r * 72 + c];
        }
    }
}

// ---------------------------------------------------------------------------
// Kernel 2: attention. 128 threads (4 warps x m32). P in registers as fp16
// (ex2.approx.f16x2, half the MUFU ops); PV in f16; row sums via ones-MMA.
// 64-row s-subtiles, 2-stage cp.async (R14 structure). 3 CTAs/SM.
// smem: Qs[128][72] + 2 stages x (K[64][72] + V[64][72]) = 55296 B.
// ---------------------------------------------------------------------------
#define AQS_O 0
#define AB_O  9216
#define STAGE_B 18432
#define ATTN_SMEM_BF (AB_O + 2 * 9216)  // 27648 bf16 = 55296 B

__device__ __forceinline__ void stage_load(uint32_t dstbase,
                                           const __nv_bfloat16* ks,
                                           const __nv_bfloat16* vs, int tid) {
#pragma unroll
    for (int it = 0; it < 4; it++) {
        int flat = it * 128 + tid;
        int r = flat >> 3, cg = flat & 7;
        uint32_t off = (uint32_t)(r * 72 + cg * 8) * 2;
        cpa16(dstbase + off,        ks + r * 64 + cg * 8);
        cpa16(dstbase + 9216 + off, vs + r * 64 + cg * 8);
    }
}

extern "C" __global__ void __launch_bounds__(128, 3)
attn_kernel(const float* __restrict__ x,
            const float* __restrict__ Wo,
            float* __restrict__ out)
{
    extern __shared__ __nv_bfloat16 smb[];
    __nv_bfloat16* Qs = smb + AQS_O;

    const int j = blockIdx.x, n = blockIdx.y;
    const int tid = threadIdx.x;
    const int warp = tid >> 5, lane = tid & 31;
    const int g = lane >> 2, c4 = lane & 3;
    const int rb = warp * 32;

    const int arow = ((lane >> 3) & 1) * 8 + (lane & 7);
    const int acol = (lane >> 4) * 8;
    const int brow = (lane >> 4) * 8 + (lane & 7);
    const int bcol = ((lane >> 3) & 1) * 8;
    const int vcol = (lane >> 4) * 8;

    const uint32_t sQ = smaddr(Qs);
    const uint32_t sB = smaddr(smb + AB_O);
    const uint32_t ONESH2 = 0x3C003C00u;   // half2(1.0, 1.0)

    const __nv_bfloat16* kbase = g_Kb + (size_t)n * T * C;
    const __nv_bfloat16* vbase = g_Vb + (size_t)n * T * C;

    const __nv_bfloat16* qsrc = g_Qb + ((size_t)n * T + j * TILE) * C;
#pragma unroll
    for (int it = 0; it < 8; it++) {
        int flat = it * 1024 + tid * 8;
        int r = flat >> 6, c = flat & 63;
        float4 v = *(const float4*)&qsrc[flat];
        *(float4*)&Qs[r * 72 + c] = v;
    }
    stage_load(sB, kbase, vbase, tid);
    CP_COMMIT();

    float oacc[2][8][4];
    float osum[2][4];   // ones-column MMA accumulators: row sums of P
#pragma unroll
    for (int mb = 0; mb < 2; mb++) {
#pragma unroll
        for (int i = 0; i < 8; i++)
#pragma unroll
            for (int k = 0; k < 4; k++) oacc[mb][i][k] = 0.f;
#pragma unroll
        for (int k = 0; k < 4; k++) osum[mb][k] = 0.f;
    }

    const uint32_t aQ0 = sQ + ((rb + arow) * 72 + acol) * 2;
    const uint32_t aQ1 = aQ0 + 16 * 72 * 2;

    for (int ss = 0; ss < NSUB; ss++) {
        if (ss > 0) __syncthreads();   // all warps done computing ss-1
        if (ss < NSUB - 1) {
            stage_load(sB + ((ss + 1) & 1) * STAGE_B,
                       kbase + (size_t)(ss + 1) * 64 * C,
                       vbase + (size_t)(ss + 1) * 64 * C, tid);
            CP_COMMIT();
            CP_WAIT(1);
        } else {
            CP_WAIT(0);
        }
        __syncthreads();

        const uint32_t sK = sB + (ss & 1) * STAGE_B;
        const uint32_t sV = sK + 9216;

        // S = Q K^T (m32 x n64 x k64), bf16
        float sacc[2][8][4];
#pragma unroll
        for (int mb = 0; mb < 2; mb++)
#pragma unroll
            for (int i = 0; i < 8; i++)
#pragma unroll
                for (int k = 0; k < 4; k++) sacc[mb][i][k] = 0.f;

#pragma unroll
        for (int ks4 = 0; ks4 < 4; ks4++) {
            uint32_t A0[4], A1[4];
            LDSM4(A0, aQ0 + ks4 * 32);
            LDSM4(A1, aQ1 + ks4 * 32);
#pragma unroll
            for (int nf2 = 0; nf2 < 4; nf2++) {
                uint32_t Bv[4];
                LDSM4(Bv, sK + ((nf2 * 16 + brow) * 72 + bcol + ks4 * 16) * 2);
                MMA_BF16(sacc[0][nf2 * 2],     A0[0], A0[1], A0[2], A0[3], Bv[0], Bv[1]);
                MMA_BF16(sacc[1][nf2 * 2],     A1[0], A1[1], A1[2], A1[3], Bv[0], Bv[1]);
                MMA_BF16(sacc[0][nf2 * 2 + 1], A0[0], A0[1], A0[2], A0[3], Bv[2], Bv[3]);
                MMA_BF16(sacc[1][nf2 * 2 + 1], A1[0], A1[1], A1[2], A1[3], Bv[2], Bv[3]);
            }
        }

        // P = exp2(S) in fp16 pairs: fragment layout == PV A-fragment.
        uint32_t pfrag[2][4][4];
#pragma unroll
        for (int mb = 0; mb < 2; mb++) {
#pragma unroll
            for (int jj = 0; jj < 4; jj++) {
                pfrag[mb][jj][0] = ex2h2(packhf(sacc[mb][2*jj][0],   sacc[mb][2*jj][1]));
                pfrag[mb][jj][1] = ex2h2(packhf(sacc[mb][2*jj][2],   sacc[mb][2*jj][3]));
                pfrag[mb][jj][2] = ex2h2(packhf(sacc[mb][2*jj+1][0], sacc[mb][2*jj+1][1]));
                pfrag[mb][jj][3] = ex2h2(packhf(sacc[mb][2*jj+1][2], sacc[mb][2*jj+1][3]));
            }
        }

        // O += P V (m32 x n64 x k64, f16) + ones-column row sums
#pragma unroll
        for (int jj = 0; jj < 4; jj++) {
#pragma unroll
            for (int nf2 = 0; nf2 < 4; nf2++) {
                uint32_t Bv[4];
                LDSM4T(Bv, sV + ((jj * 16 + arow) * 72 + nf2 * 16 + vcol) * 2);
                MMA_F16(oacc[0][nf2 * 2],     pfrag[0][jj][0], pfrag[0][jj][1],
                        pfrag[0][jj][2], pfrag[0][jj][3], Bv[0], Bv[1]);
                MMA_F16(oacc[1][nf2 * 2],     pfrag[1][jj][0], pfrag[1][jj][1],
                        pfrag[1][jj][2], pfrag[1][jj][3], Bv[0], Bv[1]);
                MMA_F16(oacc[0][nf2 * 2 + 1], pfrag[0][jj][0], pfrag[0][jj][1],
                        pfrag[0][jj][2], pfrag[0][jj][3], Bv[2], Bv[3]);
                MMA_F16(oacc[1][nf2 * 2 + 1], pfrag[1][jj][0], pfrag[1][jj][1],
                        pfrag[1][jj][2], pfrag[1][jj][3], Bv[2], Bv[3]);
            }
            MMA_F16(osum[0], pfrag[0][jj][0], pfrag[0][jj][1],
                    pfrag[0][jj][2], pfrag[0][jj][3], ONESH2, ONESH2);
            MMA_F16(osum[1], pfrag[1][jj][0], pfrag[1][jj][1],
                    pfrag[1][jj][2], pfrag[1][jj][3], ONESH2, ONESH2);
        }
    }

    // normalize: osum[mb][0] = row (rb+mb*16+g) sum, osum[mb][2] = row +8.
    // O (bf16, normalized) -> Qs (own rows) as [tq][c]
#pragma unroll
    for (int mb = 0; mb < 2; mb++) {
        int r0 = rb + mb * 16 + g, r1 = r0 + 8;
        float i0 = 1.0f / osum[mb][0];
        float i1 = 1.0f / osum[mb][2];
#pragma unroll
        for (int nf = 0; nf < 8; nf++) {
            int o = nf * 8 + 2 * c4;
            *(uint32_t*)&Qs[r0 * 72 + o] = packbf(oacc[mb][nf][0] * i0, oacc[mb][nf][1] * i0);
            *(uint32_t*)&Qs[r1 * 72 + o] = packbf(oacc[mb][nf][2] * i1, oacc[mb][nf][3] * i1);
        }
    }
    // Wo -> stage region (dead) as [o][c] bf16 stride 72
    __nv_bfloat16* Wos = smb + AB_O;
#pragma unroll
    for (int it = 0; it < 8; it++) {
        int flat = it * 512 + tid * 4;
        int o = flat >> 6, c = flat & 63;
        float4 w = *(const float4*)&Wo[flat];
        *(uint32_t*)&Wos[o * 72 + c]     = packbf(w.x, w.y);
        *(uint32_t*)&Wos[o * 72 + c + 2] = packbf(w.z, w.w);
    }
    __syncthreads();

    // D2 = O * Wo^T : m32 n64 k64 (bf16)
    const uint32_t sWo = smaddr(Wos);
    const uint32_t aO0 = sQ + ((rb + arow) * 72 + acol) * 2;
    const uint32_t aO1 = aO0 + 16 * 72 * 2;
    float pacc[2][8][4];
#pragma unroll
    for (int mb = 0; mb < 2; mb++)
#pragma unroll
        for (int i = 0; i < 8; i++)
#pragma unroll
            for (int k = 0; k < 4; k++) pacc[mb][i][k] = 0.f;

#pragma unroll
    for (int ks4 = 0; ks4 < 4; ks4++) {
        uint32_t A0[4], A1[4];
        LDSM4(A0, aO0 + ks4 * 32);
        LDSM4(A1, aO1 + ks4 * 32);
#pragma unroll
        for (int nf2 = 0; nf2 < 4; nf2++) {
            uint32_t Bv[4];
            LDSM4(Bv, sWo + ((nf2 * 16 + brow) * 72 + bcol + ks4 * 16) * 2);
            MMA_BF16(pacc[0][nf2 * 2],     A0[0], A0[1], A0[2], A0[3], Bv[0], Bv[1]);
            MMA_BF16(pacc[1][nf2 * 2],     A1[0], A1[1], A1[2], A1[3], Bv[0], Bv[1]);
            MMA_BF16(pacc[0][nf2 * 2 + 1], A0[0], A0[1], A0[2], A0[3], Bv[2], Bv[3]);
            MMA_BF16(pacc[1][nf2 * 2 + 1], A1[0], A1[1], A1[2], A1[3], Bv[2], Bv[3]);
        }
    }
    __syncthreads();   // all warps done reading Wos before Pf overwrites

    // stage transposed as fp32 [o][t] stride 132 over the stage region:
    // bytes 18432..52224 of 55296-B smem (Qs untouched).
    float* Pf = (float*)(smb + AB_O);
#pragma unroll
    for (int mb = 0; mb < 2; mb++) {
        int t0 = rb + mb * 16 + g, t1 = t0 + 8;
#pragma unroll
        for (int nf = 0; nf < 8; nf++) {
            int o = nf * 8 + 2 * c4;
            Pf[o * 132 + t0]       = pacc[mb][nf][0];
            Pf[(o + 1) * 132 + t0] = pacc[mb][nf][1];
            Pf[o * 132 + t1]       = pacc[mb][nf][2];
            Pf[(o + 1) * 132 + t1] = pacc[mb][nf][3];
        }
    }
    __syncthreads();

    // out[o][t] = proj + x, coalesced float4
    const float* xb = x + (size_t)n * C * T + j * TILE;
    float* ob = out + (size_t)n * C * T + j * TILE;
#pragma unroll
    for (int it = 0; it < 16; it++) {
        int flat = it * 512 + tid * 4;
        int o = flat >> 7, t = flat & 127;
        float4 v  = *(const float4*)&Pf[o * 132 + t];
        float4 xr = *(const float4*)&xb[o * T + t];
        float4 r  = make_float4(v.x + xr.x, v.y + xr.y, v.z + xr.z, v.w + xr.w);
        *(float4*)&ob[o * T + t] = r;
    }
}

// ---------------------------------------------------------------------------
extern "C" void kernel_launch(void* const* d_in, const int* in_sizes, int n_in,
                              void* d_out, int out_size)
{
    const float* x     = (const float*)d_in[0];
    const float* Wq    = (const float*)d_in[1];
    const float* Wk    = (const float*)d_in[2];
    const float* Wv    = (const float*)d_in[3];
    const float* Wo    = (const float*)d_in[4];
    const float* scale = (const float*)d_in[5];
    float* out = (float*)d_out;

    const int smem1 = QKV_SMEM_BF * 2;     // 63488 B
    const int smem2 = ATTN_SMEM_BF * 2;    // 55296 B
    cudaFuncSetAttribute(qkv_kernel,  cudaFuncAttributeMaxDynamicSharedMemorySize, smem1);
    cudaFuncSetAttribute(attn_kernel, cudaFuncAttributeMaxDynamicSharedMemorySize, smem2);

    dim3 grid(8, 128);
    qkv_kernel<<<grid, 128, smem1>>>(x, Wq, Wk, Wv, scale);
    attn_kernel<<<grid, 128, smem2>>>(x, Wo, out);
}